// round 2
// baseline (speedup 1.0000x reference)
#include <cuda_runtime.h>
#include <math.h>

#define NN 16384
#define DD 64
#define KK 3
#define TILE 2048

// ---------------- scratch (device globals, no allocation) ----------------
__device__ float g_x[NN * DD];      // features after LN2
__device__ float g_xnorm[NN];       // row L2 norms (clamped to 1e-8)
__device__ int   g_knn[NN * KK];    // 3 nearest neighbor indices per node
__device__ float g_ew[NN * KK];     // sigmoid cosine edge weights
__device__ float g_dis[NN];         // rsqrt(deg)
__device__ float g_t[NN * DD];      // relu(LN(gcn1 out))

__device__ __forceinline__ float wsum(float v) {
    #pragma unroll
    for (int o = 16; o > 0; o >>= 1) v += __shfl_xor_sync(0xFFFFFFFFu, v, o);
    return v;
}

// ---------------- K1: LN1 -> x2 -> LN2, store x and row norms ----------------
__global__ void ln_kernel(const float* __restrict__ in,
                          const float* __restrict__ g1, const float* __restrict__ b1,
                          const float* __restrict__ g2, const float* __restrict__ b2) {
    int i = blockIdx.x * 8 + threadIdx.y;
    int lane = threadIdx.x;
    const float* row = in + (size_t)i * DD;
    float a0 = row[lane], a1 = row[lane + 32];

    float m = wsum(a0 + a1) * (1.0f / 64.0f);
    float d0 = a0 - m, d1 = a1 - m;
    float v = wsum(d0 * d0 + d1 * d1) * (1.0f / 64.0f);
    float inv = rsqrtf(v + 1e-5f);
    float y0 = d0 * inv * g1[lane] + b1[lane];
    float y1 = d1 * inv * g1[lane + 32] + b1[lane + 32];

    y0 *= 2.0f; y1 *= 2.0f;   // x = x + x

    m = wsum(y0 + y1) * (1.0f / 64.0f);
    d0 = y0 - m; d1 = y1 - m;
    v = wsum(d0 * d0 + d1 * d1) * (1.0f / 64.0f);
    inv = rsqrtf(v + 1e-5f);
    float x0 = d0 * inv * g2[lane] + b2[lane];
    float x1 = d1 * inv * g2[lane + 32] + b2[lane + 32];

    g_x[(size_t)i * DD + lane] = x0;
    g_x[(size_t)i * DD + lane + 32] = x1;

    float s = wsum(x0 * x0 + x1 * x1);
    if (lane == 0) g_xnorm[i] = fmaxf(sqrtf(s), 1e-8f);
}

// ---------------- K2: brute-force KNN (K=3) ----------------
// 8 lanes per query, 4 queries per warp, 32 queries per 256-thread block.
// Distance arithmetic mirrors the reference exactly:
//   sq   = rn(rn(rn(x*x) + rn(y*y)) + rn(z*z))          (no fma)
//   dot  = fma(z,pz, fma(y,py, rn(x*px)))               (sgemm K-chain)
//   d    = rn(rn(sq_i + sq_j) - 2*dot)                  (2*dot exact)
__device__ __forceinline__ bool knn_lt(float d, int i, float D, int I) {
    return d < D || (d == D && i < I);
}

__global__ void knn_kernel(const float* __restrict__ coords) {
    __shared__ float4 sp[TILE];
    int q = blockIdx.x * 32 + (threadIdx.x >> 3);
    int s = threadIdx.x & 7;

    float qx = coords[q * 3 + 0];
    float qy = coords[q * 3 + 1];
    float qz = coords[q * 3 + 2];
    float qsq = __fadd_rn(__fadd_rn(__fmul_rn(qx, qx), __fmul_rn(qy, qy)),
                          __fmul_rn(qz, qz));

    float d0 = INFINITY, d1 = INFINITY, d2 = INFINITY;
    int i0 = 0x7fffffff, i1 = 0x7fffffff, i2 = 0x7fffffff;

    for (int base = 0; base < NN; base += TILE) {
        __syncthreads();
        for (int j = threadIdx.x; j < TILE; j += blockDim.x) {
            float x = coords[(base + j) * 3 + 0];
            float y = coords[(base + j) * 3 + 1];
            float z = coords[(base + j) * 3 + 2];
            float psq = __fadd_rn(__fadd_rn(__fmul_rn(x, x), __fmul_rn(y, y)),
                                  __fmul_rn(z, z));
            sp[j] = make_float4(x, y, z, psq);
        }
        __syncthreads();
        #pragma unroll 4
        for (int jj = 0; jj < TILE / 8; jj++) {
            int li = jj * 8 + s;
            float4 p = sp[li];
            int j = base + li;
            float dot = __fmaf_rn(qz, p.z, __fmaf_rn(qy, p.y, __fmul_rn(qx, p.x)));
            float t = __fadd_rn(qsq, p.w);
            float d = __fmaf_rn(-2.0f, dot, t);
            if (j == q) continue;              // exclude self
            if (d < d2) {                      // ascending j scan: strict < keeps lowest idx
                if (d < d1) {
                    if (d < d0) { d2 = d1; i2 = i1; d1 = d0; i1 = i0; d0 = d; i0 = j; }
                    else        { d2 = d1; i2 = i1; d1 = d;  i1 = j; }
                } else          { d2 = d;  i2 = j; }
            }
        }
    }

    // merge top-3 across the 8 lanes of this query (lexicographic (d, idx))
    #pragma unroll
    for (int off = 4; off >= 1; off >>= 1) {
        float e0 = __shfl_xor_sync(0xFFFFFFFFu, d0, off);
        float e1 = __shfl_xor_sync(0xFFFFFFFFu, d1, off);
        float e2 = __shfl_xor_sync(0xFFFFFFFFu, d2, off);
        int   j0 = __shfl_xor_sync(0xFFFFFFFFu, i0, off);
        int   j1 = __shfl_xor_sync(0xFFFFFFFFu, i1, off);
        int   j2 = __shfl_xor_sync(0xFFFFFFFFu, i2, off);
        float ee[3] = {e0, e1, e2};
        int   jj2[3] = {j0, j1, j2};
        #pragma unroll
        for (int r = 0; r < 3; r++) {
            float d = ee[r]; int i = jj2[r];
            if (knn_lt(d, i, d2, i2)) {
                if (knn_lt(d, i, d1, i1)) {
                    if (knn_lt(d, i, d0, i0)) { d2 = d1; i2 = i1; d1 = d0; i1 = i0; d0 = d; i0 = i; }
                    else                      { d2 = d1; i2 = i1; d1 = d;  i1 = i; }
                } else                        { d2 = d;  i2 = i; }
            }
        }
    }

    if (s == 0) {
        g_knn[q * 3 + 0] = i0;
        g_knn[q * 3 + 1] = i1;
        g_knn[q * 3 + 2] = i2;
    }
}

// ---------------- K3: edge weights (sigmoid cosine), degree, dis ----------------
__global__ void ew_kernel() {
    int i = blockIdx.x * 8 + threadIdx.y;
    int lane = threadIdx.x;
    float xi0 = g_x[(size_t)i * DD + lane];
    float xi1 = g_x[(size_t)i * DD + lane + 32];
    float ni = g_xnorm[i];

    float deg = 1.0f;   // self-loop weight 1
    float ews[KK];
    #pragma unroll
    for (int k = 0; k < KK; k++) {
        int nb = g_knn[i * 3 + k];
        float dot = wsum(xi0 * g_x[(size_t)nb * DD + lane] +
                         xi1 * g_x[(size_t)nb * DD + lane + 32]);
        float z = dot / (g_xnorm[nb] * ni);
        float e = 1.0f / (1.0f + expf(-z));
        ews[k] = e;
        deg += e;
    }
    float dis = rsqrtf(deg);
    if (lane == 0) {
        #pragma unroll
        for (int k = 0; k < KK; k++) g_ew[i * 3 + k] = ews[k];
        g_dis[i] = dis;
    }
}

// ---------------- K4/K5: fused GCN layer ----------------
// Aggregate in feature space first (linearity of @W), then one 64x64 matmul per row.
template <int EPI>
__global__ void gcn_kernel(const float* __restrict__ W, const float* __restrict__ b,
                           const float* __restrict__ lng, const float* __restrict__ lnb,
                           float* __restrict__ out) {
    __shared__ float sW[DD * DD];
    __shared__ float sZ[8][DD];
    int tid = threadIdx.y * 32 + threadIdx.x;
    for (int k = tid; k < DD * DD; k += 256) sW[k] = W[k];

    int i = blockIdx.x * 8 + threadIdx.y;
    int lane = threadIdx.x;
    const float* xin = (EPI == 1) ? g_x : g_t;

    float dii = g_dis[i];
    float cs = dii * dii;
    float z0 = cs * xin[(size_t)i * DD + lane];
    float z1 = cs * xin[(size_t)i * DD + lane + 32];
    #pragma unroll
    for (int k = 0; k < KK; k++) {
        int nb = g_knn[i * 3 + k];
        float c = g_dis[nb] * g_ew[i * 3 + k] * dii;
        z0 = fmaf(c, xin[(size_t)nb * DD + lane], z0);
        z1 = fmaf(c, xin[(size_t)nb * DD + lane + 32], z1);
    }
    sZ[threadIdx.y][lane] = z0;
    sZ[threadIdx.y][lane + 32] = z1;
    __syncthreads();

    float acc0 = 0.0f, acc1 = 0.0f;
    #pragma unroll
    for (int k = 0; k < DD; k++) {
        float zk = sZ[threadIdx.y][k];
        acc0 = fmaf(zk, sW[k * DD + lane], acc0);
        acc1 = fmaf(zk, sW[k * DD + lane + 32], acc1);
    }
    acc0 += b[lane];
    acc1 += b[lane + 32];

    if (EPI == 1) {
        float m = wsum(acc0 + acc1) * (1.0f / 64.0f);
        float e0 = acc0 - m, e1 = acc1 - m;
        float v = wsum(e0 * e0 + e1 * e1) * (1.0f / 64.0f);
        float inv = rsqrtf(v + 1e-5f);
        float r0 = fmaxf(e0 * inv * lng[lane] + lnb[lane], 0.0f);
        float r1 = fmaxf(e1 * inv * lng[lane + 32] + lnb[lane + 32], 0.0f);
        g_t[(size_t)i * DD + lane] = r0;
        g_t[(size_t)i * DD + lane + 32] = r1;
    } else {
        out[(size_t)i * DD + lane]      = fmaf(2.0f, g_x[(size_t)i * DD + lane],      acc0);
        out[(size_t)i * DD + lane + 32] = fmaf(2.0f, g_x[(size_t)i * DD + lane + 32], acc1);
    }
}

// ---------------- launch ----------------
extern "C" void kernel_launch(void* const* d_in, const int* in_sizes, int n_in,
                              void* d_out, int out_size) {
    const float* feat   = (const float*)d_in[0];   // sp_center_feat [N,64]
    const float* coords = (const float*)d_in[4];   // sp_crood [N,3]
    const float* n1g = (const float*)d_in[5];
    const float* n1b = (const float*)d_in[6];
    const float* n2g = (const float*)d_in[7];
    const float* n2b = (const float*)d_in[8];
    const float* gng = (const float*)d_in[9];
    const float* gnb = (const float*)d_in[10];
    const float* W1  = (const float*)d_in[11];
    const float* b1  = (const float*)d_in[12];
    const float* W2  = (const float*)d_in[13];
    const float* b2  = (const float*)d_in[14];
    float* out = (float*)d_out;

    dim3 th(32, 8);
    ln_kernel<<<NN / 8, th>>>(feat, n1g, n1b, n2g, n2b);
    knn_kernel<<<NN / 32, 256>>>(coords);
    ew_kernel<<<NN / 8, th>>>();
    gcn_kernel<1><<<NN / 8, th>>>(W1, b1, gng, gnb, nullptr);
    gcn_kernel<2><<<NN / 8, th>>>(W2, b2, nullptr, nullptr, out);
}

// round 3
// speedup vs baseline: 2.3164x; 2.3164x over previous
#include <cuda_runtime.h>
#include <math.h>

#define NN 16384
#define DD 64
#define KK 3
#define G 16
#define CELLS (G * G * G)   // 4096

// ---------------- scratch (device globals, no allocation) ----------------
__device__ float g_x[NN * DD];      // features after LN2
__device__ float g_xnorm[NN];       // row L2 norms
__device__ int   g_knn[NN * KK];
__device__ float g_ew[NN * KK];
__device__ float g_dis[NN];         // rsqrt(deg)
__device__ float g_t[NN * DD];      // relu(LN(gcn1 out))

__device__ int    g_cnt[CELLS];
__device__ int    g_startc[CELLS + 1];
__device__ int    g_cursor[CELLS];
__device__ float4 g_pts[NN];        // sorted (x,y,z,sq)
__device__ int    g_pid[NN];        // original index

__device__ __forceinline__ float wsum(float v) {
    #pragma unroll
    for (int o = 16; o > 0; o >>= 1) v += __shfl_xor_sync(0xFFFFFFFFu, v, o);
    return v;
}

__device__ __forceinline__ int cell_of(float x, float y, float z) {
    int cx = min(G - 1, max(0, (int)(x * (float)G)));
    int cy = min(G - 1, max(0, (int)(y * (float)G)));
    int cz = min(G - 1, max(0, (int)(z * (float)G)));
    return (cz * G + cy) * G + cx;
}

// ---------------- K1: LN1 -> x2 -> LN2 ----------------
__global__ void ln_kernel(const float* __restrict__ in,
                          const float* __restrict__ g1, const float* __restrict__ b1,
                          const float* __restrict__ g2, const float* __restrict__ b2) {
    int i = blockIdx.x * 8 + threadIdx.y;
    int lane = threadIdx.x;
    const float* row = in + (size_t)i * DD;
    float a0 = row[lane], a1 = row[lane + 32];

    float m = wsum(a0 + a1) * (1.0f / 64.0f);
    float d0 = a0 - m, d1 = a1 - m;
    float v = wsum(d0 * d0 + d1 * d1) * (1.0f / 64.0f);
    float inv = rsqrtf(v + 1e-5f);
    float y0 = d0 * inv * g1[lane] + b1[lane];
    float y1 = d1 * inv * g1[lane + 32] + b1[lane + 32];

    y0 *= 2.0f; y1 *= 2.0f;   // x = x + x

    m = wsum(y0 + y1) * (1.0f / 64.0f);
    d0 = y0 - m; d1 = y1 - m;
    v = wsum(d0 * d0 + d1 * d1) * (1.0f / 64.0f);
    inv = rsqrtf(v + 1e-5f);
    float x0 = d0 * inv * g2[lane] + b2[lane];
    float x1 = d1 * inv * g2[lane + 32] + b2[lane + 32];

    g_x[(size_t)i * DD + lane] = x0;
    g_x[(size_t)i * DD + lane + 32] = x1;

    float s = wsum(x0 * x0 + x1 * x1);
    if (lane == 0) g_xnorm[i] = fmaxf(sqrtf(s), 1e-8f);
}

// ---------------- grid build ----------------
__global__ void grid_zero() {
    int c = blockIdx.x * 256 + threadIdx.x;
    if (c < CELLS) g_cnt[c] = 0;
}

__global__ void grid_count(const float* __restrict__ coords) {
    int i = blockIdx.x * 256 + threadIdx.x;
    float x = coords[3 * i], y = coords[3 * i + 1], z = coords[3 * i + 2];
    atomicAdd(&g_cnt[cell_of(x, y, z)], 1);
}

__global__ void grid_scan() {   // single block, 1024 threads, 4 cells each
    __shared__ int sp[1024];
    int t = threadIdx.x;
    int base = t * 4;
    int loc[4]; int s = 0;
    #pragma unroll
    for (int j = 0; j < 4; j++) { loc[j] = s; s += g_cnt[base + j]; }
    sp[t] = s;
    __syncthreads();
    for (int off = 1; off < 1024; off <<= 1) {
        int v = (t >= off) ? sp[t - off] : 0;
        __syncthreads();
        sp[t] += v;
        __syncthreads();
    }
    int pre = (t == 0) ? 0 : sp[t - 1];
    #pragma unroll
    for (int j = 0; j < 4; j++) {
        int st = pre + loc[j];
        g_startc[base + j] = st;
        g_cursor[base + j] = st;
    }
    if (t == 1023) g_startc[CELLS] = sp[1023];
}

__global__ void grid_scatter(const float* __restrict__ coords) {
    int i = blockIdx.x * 256 + threadIdx.x;
    float x = coords[3 * i], y = coords[3 * i + 1], z = coords[3 * i + 2];
    // sq exactly like reference: rn(rn(rn(x*x)+rn(y*y))+rn(z*z))
    float sq = __fadd_rn(__fadd_rn(__fmul_rn(x, x), __fmul_rn(y, y)), __fmul_rn(z, z));
    int pos = atomicAdd(&g_cursor[cell_of(x, y, z)], 1);
    g_pts[pos] = make_float4(x, y, z, sq);
    g_pid[pos] = i;
}

// ---------------- K2: grid KNN (K=3), bit-exact reference distance ----------------
__device__ __forceinline__ bool knn_lt(float d, int i, float D, int I) {
    return d < D || (d == D && i < I);
}

__global__ void knn_grid(const float* __restrict__ coords) {
    int q = blockIdx.x * 64 + threadIdx.x;
    float qx = coords[3 * q], qy = coords[3 * q + 1], qz = coords[3 * q + 2];
    float qsq = __fadd_rn(__fadd_rn(__fmul_rn(qx, qx), __fmul_rn(qy, qy)),
                          __fmul_rn(qz, qz));
    int cx = min(G - 1, max(0, (int)(qx * (float)G)));
    int cy = min(G - 1, max(0, (int)(qy * (float)G)));
    int cz = min(G - 1, max(0, (int)(qz * (float)G)));
    const float h = 1.0f / (float)G;

    float d0 = INFINITY, d1 = INFINITY, d2 = INFINITY;
    int i0 = 0x7fffffff, i1 = 0x7fffffff, i2 = 0x7fffffff;

    auto eval_run = [&](int c0, int c1) {   // inclusive cell range, contiguous
        int s = g_startc[c0], e = g_startc[c1 + 1];
        for (int t = s; t < e; t++) {
            float4 p = g_pts[t];
            int j = g_pid[t];
            if (j == q) continue;
            float dot = __fmaf_rn(qz, p.z, __fmaf_rn(qy, p.y, __fmul_rn(qx, p.x)));
            float d = __fmaf_rn(-2.0f, dot, __fadd_rn(qsq, p.w));
            if (knn_lt(d, j, d2, i2)) {
                if (knn_lt(d, j, d1, i1)) {
                    if (knn_lt(d, j, d0, i0)) { d2 = d1; i2 = i1; d1 = d0; i1 = i0; d0 = d; i0 = j; }
                    else                      { d2 = d1; i2 = i1; d1 = d;  i1 = j; }
                } else                        { d2 = d;  i2 = j; }
            }
        }
    };

    int r = 1;
    while (true) {
        int z0 = max(cz - r, 0), z1 = min(cz + r, G - 1);
        int y0 = max(cy - r, 0), y1 = min(cy + r, G - 1);
        int x0 = max(cx - r, 0), x1 = min(cx + r, G - 1);
        for (int zz = z0; zz <= z1; zz++) {
            for (int yy = y0; yy <= y1; yy++) {
                bool edgeYZ = (zz == cz - r) || (zz == cz + r) ||
                              (yy == cy - r) || (yy == cy + r);
                int rowb = (zz * G + yy) * G;
                if (r > 1 && !edgeYZ) {
                    if (cx - r >= 0)     { int c = rowb + cx - r; eval_run(c, c); }
                    if (cx + r <= G - 1) { int c = rowb + cx + r; eval_run(c, c); }
                } else {
                    eval_run(rowb + x0, rowb + x1);
                }
            }
        }
        bool full = (x0 == 0 && x1 == G - 1 && y0 == 0 && y1 == G - 1 &&
                     z0 == 0 && z1 == G - 1);
        if (full) break;
        if (i2 != 0x7fffffff) {
            float m = INFINITY;
            if (cx - r > 0)     m = fminf(m, qx - (float)(cx - r) * h);
            if (cx + r < G - 1) m = fminf(m, (float)(cx + r + 1) * h - qx);
            if (cy - r > 0)     m = fminf(m, qy - (float)(cy - r) * h);
            if (cy + r < G - 1) m = fminf(m, (float)(cy + r + 1) * h - qy);
            if (cz - r > 0)     m = fminf(m, qz - (float)(cz - r) * h);
            if (cz + r < G - 1) m = fminf(m, (float)(cz + r + 1) * h - qz);
            if (m * m > d2 + 1e-5f) break;   // conservative: rounding skew <= ~3e-6
        }
        r++;
    }

    g_knn[q * 3 + 0] = i0;
    g_knn[q * 3 + 1] = i1;
    g_knn[q * 3 + 2] = i2;
}

// ---------------- K3: edge weights ----------------
__global__ void ew_kernel() {
    int i = blockIdx.x * 8 + threadIdx.y;
    int lane = threadIdx.x;
    float xi0 = g_x[(size_t)i * DD + lane];
    float xi1 = g_x[(size_t)i * DD + lane + 32];
    float ni = g_xnorm[i];

    float deg = 1.0f;
    float ews[KK];
    #pragma unroll
    for (int k = 0; k < KK; k++) {
        int nb = g_knn[i * 3 + k];
        float dot = wsum(xi0 * g_x[(size_t)nb * DD + lane] +
                         xi1 * g_x[(size_t)nb * DD + lane + 32]);
        float z = dot / (g_xnorm[nb] * ni);
        float e = 1.0f / (1.0f + expf(-z));
        ews[k] = e;
        deg += e;
    }
    float dis = rsqrtf(deg);
    if (lane == 0) {
        #pragma unroll
        for (int k = 0; k < KK; k++) g_ew[i * 3 + k] = ews[k];
        g_dis[i] = dis;
    }
}

// ---------------- K4/K5: fused GCN (32 rows/block, col-pair per thread) ----------------
template <int EPI>
__global__ void gcn_kernel(const float* __restrict__ W, const float* __restrict__ b,
                           const float* __restrict__ lng, const float* __restrict__ lnb,
                           float* __restrict__ out) {
    __shared__ float sW[DD * DD];   // 16 KB, loaded once per 32 rows
    __shared__ float sZ[8][DD];
    int tid = threadIdx.y * 32 + threadIdx.x;
    for (int k = tid; k < DD * DD; k += 256) sW[k] = W[k];
    __syncthreads();

    int lane = threadIdx.x;
    int ty = threadIdx.y;
    int c0 = 2 * lane;
    const float* xin = (EPI == 1) ? g_x : g_t;
    float2 bb = *(const float2*)&b[c0];

    #pragma unroll
    for (int rb = 0; rb < 4; rb++) {
        int i = blockIdx.x * 32 + rb * 8 + ty;

        float dii = g_dis[i];
        float cs = dii * dii;
        float2 xi = *(const float2*)&xin[(size_t)i * DD + c0];
        float z0 = cs * xi.x, z1 = cs * xi.y;
        #pragma unroll
        for (int k = 0; k < KK; k++) {
            int nb = g_knn[i * 3 + k];
            float c = g_dis[nb] * g_ew[i * 3 + k] * dii;
            float2 xn = *(const float2*)&xin[(size_t)nb * DD + c0];
            z0 = fmaf(c, xn.x, z0);
            z1 = fmaf(c, xn.y, z1);
        }
        sZ[ty][c0] = z0;
        sZ[ty][c0 + 1] = z1;
        __syncwarp();

        float acc0 = 0.0f, acc1 = 0.0f;
        #pragma unroll
        for (int k = 0; k < DD; k++) {
            float zk = sZ[ty][k];
            float2 w = *(const float2*)&sW[k * DD + c0];
            acc0 = fmaf(zk, w.x, acc0);
            acc1 = fmaf(zk, w.y, acc1);
        }
        acc0 += bb.x;
        acc1 += bb.y;

        if (EPI == 1) {
            float m = wsum(acc0 + acc1) * (1.0f / 64.0f);
            float e0 = acc0 - m, e1 = acc1 - m;
            float v = wsum(e0 * e0 + e1 * e1) * (1.0f / 64.0f);
            float inv = rsqrtf(v + 1e-5f);
            float2 o;
            o.x = fmaxf(e0 * inv * lng[c0] + lnb[c0], 0.0f);
            o.y = fmaxf(e1 * inv * lng[c0 + 1] + lnb[c0 + 1], 0.0f);
            *(float2*)&g_t[(size_t)i * DD + c0] = o;
        } else {
            float2 xv = *(const float2*)&g_x[(size_t)i * DD + c0];
            float2 o;
            o.x = fmaf(2.0f, xv.x, acc0);
            o.y = fmaf(2.0f, xv.y, acc1);
            *(float2*)&out[(size_t)i * DD + c0] = o;
        }
        __syncwarp();   // sZ reuse in next rb
    }
}

// ---------------- launch ----------------
extern "C" void kernel_launch(void* const* d_in, const int* in_sizes, int n_in,
                              void* d_out, int out_size) {
    const float* feat   = (const float*)d_in[0];
    const float* coords = (const float*)d_in[4];
    const float* n1g = (const float*)d_in[5];
    const float* n1b = (const float*)d_in[6];
    const float* n2g = (const float*)d_in[7];
    const float* n2b = (const float*)d_in[8];
    const float* gng = (const float*)d_in[9];
    const float* gnb = (const float*)d_in[10];
    const float* W1  = (const float*)d_in[11];
    const float* b1  = (const float*)d_in[12];
    const float* W2  = (const float*)d_in[13];
    const float* b2  = (const float*)d_in[14];
    float* out = (float*)d_out;

    dim3 th(32, 8);
    ln_kernel<<<NN / 8, th>>>(feat, n1g, n1b, n2g, n2b);
    grid_zero<<<CELLS / 256, 256>>>();
    grid_count<<<NN / 256, 256>>>(coords);
    grid_scan<<<1, 1024>>>();
    grid_scatter<<<NN / 256, 256>>>(coords);
    knn_grid<<<NN / 64, 64>>>(coords);
    ew_kernel<<<NN / 8, th>>>();
    gcn_kernel<1><<<NN / 32, th>>>(W1, b1, gng, gnb, nullptr);
    gcn_kernel<2><<<NN / 32, th>>>(W2, b2, nullptr, nullptr, out);
}

// round 5
// speedup vs baseline: 3.3738x; 1.4565x over previous
#include <cuda_runtime.h>
#include <math.h>

#define NN 16384
#define DD 64
#define KK 3
#define G 16
#define CELLS (G * G * G)   // 4096
#define CAP 48              // bucket capacity (P(overflow) ~ 1e-40 for Poisson(4))

// ---------------- scratch (device globals, no allocation) ----------------
__device__ float g_x[NN * DD];      // features after LN2
__device__ float g_xnorm[NN];       // row L2 norms
__device__ int   g_knn[NN * KK];
__device__ float g_ew[NN * KK];
__device__ float g_dis[NN];         // rsqrt(deg)
__device__ float g_t[NN * DD];      // relu(LN(gcn1 out))

__device__ int    g_cnt[CELLS];
__device__ float4 g_bkt[CELLS * CAP];   // (x, y, z, idx-as-bits)

__device__ __forceinline__ float wsum(float v) {
    #pragma unroll
    for (int o = 16; o > 0; o >>= 1) v += __shfl_xor_sync(0xFFFFFFFFu, v, o);
    return v;
}

__device__ __forceinline__ int cell_of(float x, float y, float z) {
    int cx = min(G - 1, max(0, (int)(x * (float)G)));
    int cy = min(G - 1, max(0, (int)(y * (float)G)));
    int cz = min(G - 1, max(0, (int)(z * (float)G)));
    return (cz * G + cy) * G + cx;
}

// ---------------- grid build ----------------
__global__ void grid_zero() {
    g_cnt[blockIdx.x * 256 + threadIdx.x] = 0;
}

__global__ void grid_build(const float* __restrict__ coords) {
    int i = blockIdx.x * 256 + threadIdx.x;
    float x = coords[3 * i], y = coords[3 * i + 1], z = coords[3 * i + 2];
    int c = cell_of(x, y, z);
    int pos = atomicAdd(&g_cnt[c], 1);
    if (pos < CAP) g_bkt[c * CAP + pos] = make_float4(x, y, z, __int_as_float(i));
}

// ---------------- K1: LN1 -> x2 -> LN2 ----------------
__global__ void ln_kernel(const float* __restrict__ in,
                          const float* __restrict__ g1, const float* __restrict__ b1,
                          const float* __restrict__ g2, const float* __restrict__ b2) {
    int i = blockIdx.x * 8 + threadIdx.y;
    int lane = threadIdx.x;
    const float* row = in + (size_t)i * DD;
    float a0 = row[lane], a1 = row[lane + 32];

    float m = wsum(a0 + a1) * (1.0f / 64.0f);
    float d0 = a0 - m, d1 = a1 - m;
    float v = wsum(d0 * d0 + d1 * d1) * (1.0f / 64.0f);
    float inv = rsqrtf(v + 1e-5f);
    float y0 = d0 * inv * g1[lane] + b1[lane];
    float y1 = d1 * inv * g1[lane + 32] + b1[lane + 32];

    y0 *= 2.0f; y1 *= 2.0f;   // x = x + x

    m = wsum(y0 + y1) * (1.0f / 64.0f);
    d0 = y0 - m; d1 = y1 - m;
    v = wsum(d0 * d0 + d1 * d1) * (1.0f / 64.0f);
    inv = rsqrtf(v + 1e-5f);
    float x0 = d0 * inv * g2[lane] + b2[lane];
    float x1 = d1 * inv * g2[lane + 32] + b2[lane + 32];

    g_x[(size_t)i * DD + lane] = x0;
    g_x[(size_t)i * DD + lane + 32] = x1;

    float s = wsum(x0 * x0 + x1 * x1);
    if (lane == 0) g_xnorm[i] = fmaxf(sqrtf(s), 1e-8f);
}

// ---------------- K2: grid KNN, warp per query ----------------
// Per-lane lists stay live and DISJOINT across the whole search (each candidate
// is evaluated by exactly one lane, each cell visited once). Ring-boundary
// merges operate on COPIES only (for the stopping test and final output), so
// duplicate re-insertion (the round-4 bug) cannot occur.
__device__ __forceinline__ bool knn_lt(float d, int i, float D, int I) {
    return d < D || (d == D && i < I);
}

__global__ void knn_grid(const float* __restrict__ coords) {
    int q = (blockIdx.x * blockDim.x + threadIdx.x) >> 5;
    int lane = threadIdx.x & 31;

    float qx = coords[3 * q], qy = coords[3 * q + 1], qz = coords[3 * q + 2];
    float qsq = __fadd_rn(__fadd_rn(__fmul_rn(qx, qx), __fmul_rn(qy, qy)),
                          __fmul_rn(qz, qz));
    int cx = min(G - 1, max(0, (int)(qx * (float)G)));
    int cy = min(G - 1, max(0, (int)(qy * (float)G)));
    int cz = min(G - 1, max(0, (int)(qz * (float)G)));
    const float h = 1.0f / (float)G;

    // per-lane disjoint lists
    float d0 = INFINITY, d1 = INFINITY, d2 = INFINITY;
    int i0 = 0x7fffffff, i1 = 0x7fffffff, i2 = 0x7fffffff;

    auto eval_cell = [&](int c) {
        int cnt = min(g_cnt[c], CAP);
        const float4* bp = &g_bkt[c * CAP];
        for (int t = lane; t < cnt; t += 32) {
            float4 p = bp[t];
            int j = __float_as_int(p.w);
            if (j == q) continue;
            float psq = __fadd_rn(__fadd_rn(__fmul_rn(p.x, p.x), __fmul_rn(p.y, p.y)),
                                  __fmul_rn(p.z, p.z));
            float dot = __fmaf_rn(qz, p.z, __fmaf_rn(qy, p.y, __fmul_rn(qx, p.x)));
            float d = __fmaf_rn(-2.0f, dot, __fadd_rn(qsq, psq));
            if (knn_lt(d, j, d2, i2)) {
                if (knn_lt(d, j, d1, i1)) {
                    if (knn_lt(d, j, d0, i0)) { d2 = d1; i2 = i1; d1 = d0; i1 = i0; d0 = d; i0 = j; }
                    else                      { d2 = d1; i2 = i1; d1 = d;  i1 = j; }
                } else                        { d2 = d;  i2 = j; }
            }
        }
    };

    // merged copies (recomputed from the live lists at each ring boundary)
    float m0, m1, m2; int n0, n1, n2;
    auto merge_copies = [&]() {
        m0 = d0; m1 = d1; m2 = d2; n0 = i0; n1 = i1; n2 = i2;
        #pragma unroll
        for (int off = 16; off >= 1; off >>= 1) {
            float e0 = __shfl_xor_sync(0xFFFFFFFFu, m0, off);
            float e1 = __shfl_xor_sync(0xFFFFFFFFu, m1, off);
            float e2 = __shfl_xor_sync(0xFFFFFFFFu, m2, off);
            int   j0 = __shfl_xor_sync(0xFFFFFFFFu, n0, off);
            int   j1 = __shfl_xor_sync(0xFFFFFFFFu, n1, off);
            int   j2 = __shfl_xor_sync(0xFFFFFFFFu, n2, off);
            float ee[3] = {e0, e1, e2};
            int   jj[3] = {j0, j1, j2};
            #pragma unroll
            for (int r = 0; r < 3; r++) {
                float d = ee[r]; int i = jj[r];
                if (knn_lt(d, i, m2, n2)) {
                    if (knn_lt(d, i, m1, n1)) {
                        if (knn_lt(d, i, m0, n0)) { m2 = m1; n2 = n1; m1 = m0; n1 = n0; m0 = d; n0 = i; }
                        else                      { m2 = m1; n2 = n1; m1 = d;  n1 = i; }
                    } else                        { m2 = d;  n2 = i; }
                }
            }
        }
    };

    int r = 1;
    while (true) {
        int z0 = max(cz - r, 0), z1 = min(cz + r, G - 1);
        int y0 = max(cy - r, 0), y1 = min(cy + r, G - 1);
        int x0 = max(cx - r, 0), x1 = min(cx + r, G - 1);
        for (int zz = z0; zz <= z1; zz++) {
            for (int yy = y0; yy <= y1; yy++) {
                bool edgeYZ = (zz == cz - r) || (zz == cz + r) ||
                              (yy == cy - r) || (yy == cy + r);
                int rowb = (zz * G + yy) * G;
                if (r > 1 && !edgeYZ) {
                    if (cx - r >= 0)     eval_cell(rowb + cx - r);
                    if (cx + r <= G - 1) eval_cell(rowb + cx + r);
                } else {
                    for (int xx = x0; xx <= x1; xx++) eval_cell(rowb + xx);
                }
            }
        }
        merge_copies();
        bool full = (x0 == 0 && x1 == G - 1 && y0 == 0 && y1 == G - 1 &&
                     z0 == 0 && z1 == G - 1);
        if (full) break;
        if (n2 != 0x7fffffff) {
            float m = INFINITY;
            if (cx - r > 0)     m = fminf(m, qx - (float)(cx - r) * h);
            if (cx + r < G - 1) m = fminf(m, (float)(cx + r + 1) * h - qx);
            if (cy - r > 0)     m = fminf(m, qy - (float)(cy - r) * h);
            if (cy + r < G - 1) m = fminf(m, (float)(cy + r + 1) * h - qy);
            if (cz - r > 0)     m = fminf(m, qz - (float)(cz - r) * h);
            if (cz + r < G - 1) m = fminf(m, (float)(cz + r + 1) * h - qz);
            if (m * m > m2 + 1e-5f) break;   // conservative: rounding skew <= ~3e-6
        }
        r++;
    }

    if (lane == 0) {
        g_knn[q * 3 + 0] = n0;
        g_knn[q * 3 + 1] = n1;
        g_knn[q * 3 + 2] = n2;
    }
}

// ---------------- K3: edge weights ----------------
__global__ void ew_kernel() {
    int i = blockIdx.x * 8 + threadIdx.y;
    int lane = threadIdx.x;
    float xi0 = g_x[(size_t)i * DD + lane];
    float xi1 = g_x[(size_t)i * DD + lane + 32];
    float ni = g_xnorm[i];

    float deg = 1.0f;
    float ews[KK];
    #pragma unroll
    for (int k = 0; k < KK; k++) {
        int nb = g_knn[i * 3 + k];
        float dot = wsum(xi0 * g_x[(size_t)nb * DD + lane] +
                         xi1 * g_x[(size_t)nb * DD + lane + 32]);
        float z = dot / (g_xnorm[nb] * ni);
        float e = 1.0f / (1.0f + expf(-z));
        ews[k] = e;
        deg += e;
    }
    float dis = rsqrtf(deg);
    if (lane == 0) {
        #pragma unroll
        for (int k = 0; k < KK; k++) g_ew[i * 3 + k] = ews[k];
        g_dis[i] = dis;
    }
}

// ---------------- K4/K5: fused GCN (32 rows/block, col-pair per thread) ----------------
template <int EPI>
__global__ void gcn_kernel(const float* __restrict__ W, const float* __restrict__ b,
                           const float* __restrict__ lng, const float* __restrict__ lnb,
                           float* __restrict__ out) {
    __shared__ float sW[DD * DD];
    __shared__ float sZ[8][DD];
    int tid = threadIdx.y * 32 + threadIdx.x;
    for (int k = tid; k < DD * DD; k += 256) sW[k] = W[k];
    __syncthreads();

    int lane = threadIdx.x;
    int ty = threadIdx.y;
    int c0 = 2 * lane;
    const float* xin = (EPI == 1) ? g_x : g_t;
    float2 bb = *(const float2*)&b[c0];

    #pragma unroll
    for (int rb = 0; rb < 4; rb++) {
        int i = blockIdx.x * 32 + rb * 8 + ty;

        float dii = g_dis[i];
        float cs = dii * dii;
        float2 xi = *(const float2*)&xin[(size_t)i * DD + c0];
        float z0 = cs * xi.x, z1 = cs * xi.y;
        #pragma unroll
        for (int k = 0; k < KK; k++) {
            int nb = g_knn[i * 3 + k];
            float c = g_dis[nb] * g_ew[i * 3 + k] * dii;
            float2 xn = *(const float2*)&xin[(size_t)nb * DD + c0];
            z0 = fmaf(c, xn.x, z0);
            z1 = fmaf(c, xn.y, z1);
        }
        sZ[ty][c0] = z0;
        sZ[ty][c0 + 1] = z1;
        __syncwarp();

        float acc0 = 0.0f, acc1 = 0.0f;
        #pragma unroll
        for (int k = 0; k < DD; k++) {
            float zk = sZ[ty][k];
            float2 w = *(const float2*)&sW[k * DD + c0];
            acc0 = fmaf(zk, w.x, acc0);
            acc1 = fmaf(zk, w.y, acc1);
        }
        acc0 += bb.x;
        acc1 += bb.y;

        if (EPI == 1) {
            float m = wsum(acc0 + acc1) * (1.0f / 64.0f);
            float e0 = acc0 - m, e1 = acc1 - m;
            float v = wsum(e0 * e0 + e1 * e1) * (1.0f / 64.0f);
            float inv = rsqrtf(v + 1e-5f);
            float2 o;
            o.x = fmaxf(e0 * inv * lng[c0] + lnb[c0], 0.0f);
            o.y = fmaxf(e1 * inv * lng[c0 + 1] + lnb[c0 + 1], 0.0f);
            *(float2*)&g_t[(size_t)i * DD + c0] = o;
        } else {
            float2 xv = *(const float2*)&g_x[(size_t)i * DD + c0];
            float2 o;
            o.x = fmaf(2.0f, xv.x, acc0);
            o.y = fmaf(2.0f, xv.y, acc1);
            *(float2*)&out[(size_t)i * DD + c0] = o;
        }
        __syncwarp();
    }
}

// ---------------- launch ----------------
extern "C" void kernel_launch(void* const* d_in, const int* in_sizes, int n_in,
                              void* d_out, int out_size) {
    const float* feat   = (const float*)d_in[0];
    const float* coords = (const float*)d_in[4];
    const float* n1g = (const float*)d_in[5];
    const float* n1b = (const float*)d_in[6];
    const float* n2g = (const float*)d_in[7];
    const float* n2b = (const float*)d_in[8];
    const float* gng = (const float*)d_in[9];
    const float* gnb = (const float*)d_in[10];
    const float* W1  = (const float*)d_in[11];
    const float* b1  = (const float*)d_in[12];
    const float* W2  = (const float*)d_in[13];
    const float* b2  = (const float*)d_in[14];
    float* out = (float*)d_out;

    dim3 th(32, 8);
    grid_zero<<<CELLS / 256, 256>>>();
    grid_build<<<NN / 256, 256>>>(coords);
    ln_kernel<<<NN / 8, th>>>(feat, n1g, n1b, n2g, n2b);
    knn_grid<<<NN * 32 / 256, 256>>>(coords);
    ew_kernel<<<NN / 8, th>>>();
    gcn_kernel<1><<<NN / 32, th>>>(W1, b1, gng, gnb, nullptr);
    gcn_kernel<2><<<NN / 32, th>>>(W2, b2, nullptr, nullptr, out);
}

// round 6
// speedup vs baseline: 4.1989x; 1.2446x over previous
#include <cuda_runtime.h>
#include <math.h>

#define NN 16384
#define DD 64
#define KK 3
#define G 16
#define CELLS (G * G * G)   // 4096
#define CAP 48              // bucket capacity (P(overflow) ~ 1e-40 for Poisson(4))

// ---------------- scratch (device globals, no allocation) ----------------
__device__ float g_x[NN * DD];      // features after LN2
__device__ float g_xnorm[NN];       // row L2 norms
__device__ int   g_knn[NN * KK];
__device__ float g_ew[NN * KK];
__device__ float g_dis[NN];         // rsqrt(deg)
__device__ float g_t[NN * DD];      // relu(LN(gcn1 out))

__device__ int    g_cnt[CELLS];
__device__ float4 g_bkt[CELLS * CAP];   // (x, y, z, idx-as-bits)

__device__ __forceinline__ float wsum(float v) {
    #pragma unroll
    for (int o = 16; o > 0; o >>= 1) v += __shfl_xor_sync(0xFFFFFFFFu, v, o);
    return v;
}

__device__ __forceinline__ int cell_of(float x, float y, float z) {
    int cx = min(G - 1, max(0, (int)(x * (float)G)));
    int cy = min(G - 1, max(0, (int)(y * (float)G)));
    int cz = min(G - 1, max(0, (int)(z * (float)G)));
    return (cz * G + cy) * G + cx;
}

// ---------------- grid build ----------------
__global__ void grid_zero() {
    g_cnt[blockIdx.x * 256 + threadIdx.x] = 0;
}

__global__ void grid_build(const float* __restrict__ coords) {
    int i = blockIdx.x * 256 + threadIdx.x;
    float x = coords[3 * i], y = coords[3 * i + 1], z = coords[3 * i + 2];
    int c = cell_of(x, y, z);
    int pos = atomicAdd(&g_cnt[c], 1);
    if (pos < CAP) g_bkt[c * CAP + pos] = make_float4(x, y, z, __int_as_float(i));
}

// ---------------- K1: LN1 -> x2 -> LN2 ----------------
__global__ void ln_kernel(const float* __restrict__ in,
                          const float* __restrict__ g1, const float* __restrict__ b1,
                          const float* __restrict__ g2, const float* __restrict__ b2) {
    int i = blockIdx.x * 8 + threadIdx.y;
    int lane = threadIdx.x;
    const float* row = in + (size_t)i * DD;
    float a0 = row[lane], a1 = row[lane + 32];

    float m = wsum(a0 + a1) * (1.0f / 64.0f);
    float d0 = a0 - m, d1 = a1 - m;
    float v = wsum(d0 * d0 + d1 * d1) * (1.0f / 64.0f);
    float inv = rsqrtf(v + 1e-5f);
    float y0 = d0 * inv * g1[lane] + b1[lane];
    float y1 = d1 * inv * g1[lane + 32] + b1[lane + 32];

    y0 *= 2.0f; y1 *= 2.0f;   // x = x + x

    m = wsum(y0 + y1) * (1.0f / 64.0f);
    d0 = y0 - m; d1 = y1 - m;
    v = wsum(d0 * d0 + d1 * d1) * (1.0f / 64.0f);
    inv = rsqrtf(v + 1e-5f);
    float x0 = d0 * inv * g2[lane] + b2[lane];
    float x1 = d1 * inv * g2[lane + 32] + b2[lane + 32];

    g_x[(size_t)i * DD + lane] = x0;
    g_x[(size_t)i * DD + lane + 32] = x1;

    float s = wsum(x0 * x0 + x1 * x1);
    if (lane == 0) g_xnorm[i] = fmaxf(sqrtf(s), 1e-8f);
}

// ---------------- K2: grid KNN, warp per query, LANE PER CELL ----------------
// Each cell of the search region is assigned to exactly one lane; that lane
// evaluates all of the cell's points into its private top-3. Per-lane lists
// stay disjoint across the whole search (cell visited once, point evaluated by
// one lane once). Ring-boundary merges operate on COPIES only.
// Distance arithmetic mirrors the reference bit-exactly.
__device__ __forceinline__ bool knn_lt(float d, int i, float D, int I) {
    return d < D || (d == D && i < I);
}

__global__ void knn_grid(const float* __restrict__ coords) {
    int q = blockIdx.x * 8 + threadIdx.y;
    int lane = threadIdx.x;

    float qx = coords[3 * q], qy = coords[3 * q + 1], qz = coords[3 * q + 2];
    float qsq = __fadd_rn(__fadd_rn(__fmul_rn(qx, qx), __fmul_rn(qy, qy)),
                          __fmul_rn(qz, qz));
    int cx = min(G - 1, max(0, (int)(qx * (float)G)));
    int cy = min(G - 1, max(0, (int)(qy * (float)G)));
    int cz = min(G - 1, max(0, (int)(qz * (float)G)));
    const float h = 1.0f / (float)G;

    // per-lane disjoint lists
    float d0 = INFINITY, d1 = INFINITY, d2 = INFINITY;
    int i0 = 0x7fffffff, i1 = 0x7fffffff, i2 = 0x7fffffff;

    auto eval_cell_all = [&](int c) {   // this lane evaluates ALL points of cell c
        int cnt = min(g_cnt[c], CAP);
        const float4* bp = &g_bkt[c * CAP];
        for (int t = 0; t < cnt; t++) {
            float4 p = bp[t];
            int j = __float_as_int(p.w);
            if (j == q) continue;
            float psq = __fadd_rn(__fadd_rn(__fmul_rn(p.x, p.x), __fmul_rn(p.y, p.y)),
                                  __fmul_rn(p.z, p.z));
            float dot = __fmaf_rn(qz, p.z, __fmaf_rn(qy, p.y, __fmul_rn(qx, p.x)));
            float d = __fmaf_rn(-2.0f, dot, __fadd_rn(qsq, psq));
            if (knn_lt(d, j, d2, i2)) {
                if (knn_lt(d, j, d1, i1)) {
                    if (knn_lt(d, j, d0, i0)) { d2 = d1; i2 = i1; d1 = d0; i1 = i0; d0 = d; i0 = j; }
                    else                      { d2 = d1; i2 = i1; d1 = d;  i1 = j; }
                } else                        { d2 = d;  i2 = j; }
            }
        }
    };

    // merged copies (recomputed from the live lists at each ring boundary)
    float m0, m1, m2; int n0, n1, n2;
    auto merge_copies = [&]() {
        m0 = d0; m1 = d1; m2 = d2; n0 = i0; n1 = i1; n2 = i2;
        #pragma unroll
        for (int off = 16; off >= 1; off >>= 1) {
            float e0 = __shfl_xor_sync(0xFFFFFFFFu, m0, off);
            float e1 = __shfl_xor_sync(0xFFFFFFFFu, m1, off);
            float e2 = __shfl_xor_sync(0xFFFFFFFFu, m2, off);
            int   j0 = __shfl_xor_sync(0xFFFFFFFFu, n0, off);
            int   j1 = __shfl_xor_sync(0xFFFFFFFFu, n1, off);
            int   j2 = __shfl_xor_sync(0xFFFFFFFFu, n2, off);
            float ee[3] = {e0, e1, e2};
            int   jj[3] = {j0, j1, j2};
            #pragma unroll
            for (int r = 0; r < 3; r++) {
                float d = ee[r]; int i = jj[r];
                if (knn_lt(d, i, m2, n2)) {
                    if (knn_lt(d, i, m1, n1)) {
                        if (knn_lt(d, i, m0, n0)) { m2 = m1; n2 = n1; m1 = m0; n1 = n0; m0 = d; n0 = i; }
                        else                      { m2 = m1; n2 = n1; m1 = d;  n1 = i; }
                    } else                        { m2 = d;  n2 = i; }
                }
            }
        }
    };

    auto stop_ok = [&](int r) -> bool {   // conservative geometric stopping bound
        if (n2 == 0x7fffffff) return false;
        float m = INFINITY;
        if (cx - r > 0)     m = fminf(m, qx - (float)(cx - r) * h);
        if (cx + r < G - 1) m = fminf(m, (float)(cx + r + 1) * h - qx);
        if (cy - r > 0)     m = fminf(m, qy - (float)(cy - r) * h);
        if (cy + r < G - 1) m = fminf(m, (float)(cy + r + 1) * h - qy);
        if (cz - r > 0)     m = fminf(m, qz - (float)(cz - r) * h);
        if (cz + r < G - 1) m = fminf(m, (float)(cz + r + 1) * h - qz);
        return m * m > m2 + 1e-5f;        // rounding skew <= ~3e-6
    };

    // ---- ring 1: 27 cells, one per lane (compile-time decode) ----
    if (lane < 27) {
        int dz = lane / 9 - 1;
        int dy = (lane % 9) / 3 - 1;
        int dx = lane % 3 - 1;
        int xx = cx + dx, yy = cy + dy, zz = cz + dz;
        if (xx >= 0 && xx < G && yy >= 0 && yy < G && zz >= 0 && zz < G)
            eval_cell_all((zz * G + yy) * G + xx);
    }
    merge_copies();

    bool done;
    {
        bool full = (cx - 1 <= 0 && cx + 1 >= G - 1 && cy - 1 <= 0 && cy + 1 >= G - 1 &&
                     cz - 1 <= 0 && cz + 1 >= G - 1);
        done = full || stop_ok(1);
    }

    // ---- rings r >= 2 (rare): flat shell enumeration, lanes stride cells ----
    for (int r = 2; !done; r++) {
        int side = 2 * r + 1;
        int ncell = side * side * side;
        for (int t = lane; t < ncell; t += 32) {
            int dz = t / (side * side) - r;
            int rem = t % (side * side);
            int dy = rem / side - r;
            int dx = rem % side - r;
            int ma = max(abs(dx), max(abs(dy), abs(dz)));
            if (ma < r) continue;                      // interior already scanned
            int xx = cx + dx, yy = cy + dy, zz = cz + dz;
            if (xx < 0 || xx >= G || yy < 0 || yy >= G || zz < 0 || zz >= G) continue;
            eval_cell_all((zz * G + yy) * G + xx);
        }
        merge_copies();
        bool full = (cx - r <= 0 && cx + r >= G - 1 && cy - r <= 0 && cy + r >= G - 1 &&
                     cz - r <= 0 && cz + r >= G - 1);
        done = full || stop_ok(r);
    }

    if (lane == 0) {
        g_knn[q * 3 + 0] = n0;
        g_knn[q * 3 + 1] = n1;
        g_knn[q * 3 + 2] = n2;
    }
}

// ---------------- K3: edge weights ----------------
__global__ void ew_kernel() {
    int i = blockIdx.x * 8 + threadIdx.y;
    int lane = threadIdx.x;
    float xi0 = g_x[(size_t)i * DD + lane];
    float xi1 = g_x[(size_t)i * DD + lane + 32];
    float ni = g_xnorm[i];

    float deg = 1.0f;
    float ews[KK];
    #pragma unroll
    for (int k = 0; k < KK; k++) {
        int nb = g_knn[i * 3 + k];
        float dot = wsum(xi0 * g_x[(size_t)nb * DD + lane] +
                         xi1 * g_x[(size_t)nb * DD + lane + 32]);
        float z = dot / (g_xnorm[nb] * ni);
        float e = 1.0f / (1.0f + expf(-z));
        ews[k] = e;
        deg += e;
    }
    float dis = rsqrtf(deg);
    if (lane == 0) {
        #pragma unroll
        for (int k = 0; k < KK; k++) g_ew[i * 3 + k] = ews[k];
        g_dis[i] = dis;
    }
}

// ---------------- K4/K5: fused GCN (32 rows/block, col-pair per thread) ----------------
template <int EPI>
__global__ void gcn_kernel(const float* __restrict__ W, const float* __restrict__ b,
                           const float* __restrict__ lng, const float* __restrict__ lnb,
                           float* __restrict__ out) {
    __shared__ float sW[DD * DD];
    __shared__ float sZ[8][DD];
    int tid = threadIdx.y * 32 + threadIdx.x;
    for (int k = tid; k < DD * DD; k += 256) sW[k] = W[k];
    __syncthreads();

    int lane = threadIdx.x;
    int ty = threadIdx.y;
    int c0 = 2 * lane;
    const float* xin = (EPI == 1) ? g_x : g_t;
    float2 bb = *(const float2*)&b[c0];

    #pragma unroll
    for (int rb = 0; rb < 4; rb++) {
        int i = blockIdx.x * 32 + rb * 8 + ty;

        float dii = g_dis[i];
        float cs = dii * dii;
        float2 xi = *(const float2*)&xin[(size_t)i * DD + c0];
        float z0 = cs * xi.x, z1 = cs * xi.y;
        #pragma unroll
        for (int k = 0; k < KK; k++) {
            int nb = g_knn[i * 3 + k];
            float c = g_dis[nb] * g_ew[i * 3 + k] * dii;
            float2 xn = *(const float2*)&xin[(size_t)nb * DD + c0];
            z0 = fmaf(c, xn.x, z0);
            z1 = fmaf(c, xn.y, z1);
        }
        sZ[ty][c0] = z0;
        sZ[ty][c0 + 1] = z1;
        __syncwarp();

        float acc0 = 0.0f, acc1 = 0.0f;
        #pragma unroll
        for (int k = 0; k < DD; k++) {
            float zk = sZ[ty][k];
            float2 w = *(const float2*)&sW[k * DD + c0];
            acc0 = fmaf(zk, w.x, acc0);
            acc1 = fmaf(zk, w.y, acc1);
        }
        acc0 += bb.x;
        acc1 += bb.y;

        if (EPI == 1) {
            float m = wsum(acc0 + acc1) * (1.0f / 64.0f);
            float e0 = acc0 - m, e1 = acc1 - m;
            float v = wsum(e0 * e0 + e1 * e1) * (1.0f / 64.0f);
            float inv = rsqrtf(v + 1e-5f);
            float2 o;
            o.x = fmaxf(e0 * inv * lng[c0] + lnb[c0], 0.0f);
            o.y = fmaxf(e1 * inv * lng[c0 + 1] + lnb[c0 + 1], 0.0f);
            *(float2*)&g_t[(size_t)i * DD + c0] = o;
        } else {
            float2 xv = *(const float2*)&g_x[(size_t)i * DD + c0];
            float2 o;
            o.x = fmaf(2.0f, xv.x, acc0);
            o.y = fmaf(2.0f, xv.y, acc1);
            *(float2*)&out[(size_t)i * DD + c0] = o;
        }
        __syncwarp();
    }
}

// ---------------- launch ----------------
extern "C" void kernel_launch(void* const* d_in, const int* in_sizes, int n_in,
                              void* d_out, int out_size) {
    const float* feat   = (const float*)d_in[0];
    const float* coords = (const float*)d_in[4];
    const float* n1g = (const float*)d_in[5];
    const float* n1b = (const float*)d_in[6];
    const float* n2g = (const float*)d_in[7];
    const float* n2b = (const float*)d_in[8];
    const float* gng = (const float*)d_in[9];
    const float* gnb = (const float*)d_in[10];
    const float* W1  = (const float*)d_in[11];
    const float* b1  = (const float*)d_in[12];
    const float* W2  = (const float*)d_in[13];
    const float* b2  = (const float*)d_in[14];
    float* out = (float*)d_out;

    dim3 th(32, 8);
    grid_zero<<<CELLS / 256, 256>>>();
    grid_build<<<NN / 256, 256>>>(coords);
    ln_kernel<<<NN / 8, th>>>(feat, n1g, n1b, n2g, n2b);
    knn_grid<<<NN / 8, th>>>(coords);
    ew_kernel<<<NN / 8, th>>>();
    gcn_kernel<1><<<NN / 32, th>>>(W1, b1, gng, gnb, nullptr);
    gcn_kernel<2><<<NN / 32, th>>>(W2, b2, nullptr, nullptr, out);
}